// round 14
// baseline (speedup 1.0000x reference)
#include <cuda_runtime.h>
#include <cuda_fp16.h>
#include <cstdint>

#define B_   128
#define T_   196
#define TT_  392      // 2*T
#define ENC_ 1024
#define DEC_ 512
#define V_   98
#define M_   294

// GEMM tiling: CTA tile 128x64, warp tile 32x32, 8 warps, 2-stage pipeline
#define BK_   64           // fp16 K elements per chunk (128 bytes)
#define NCH_  16           // 1024 / 64
#define STG_BYTES 24576    // per stage: A 16KB (128x128B) + B 8KB (64x128B)
#define B_OFF  16384
#define SMEM_TOTAL (2 * STG_BYTES)   // 49152

#define NGEMM_ 784          // 98 m-tiles x 8 n-tiles
#define NFILL_ 96
#define NWORK_ (M_ * B_)

// prep kernel block ranges
#define PREP_X_   3136     // 12544 rows / 4 rows per block
#define PREP_W_   128      // 512 / 4
#define PREP_TAB_ 196      // 784 table rows / 4
#define PREP_MAP_ 128
#define PREP_GRID_ (PREP_X_ + PREP_W_ + PREP_TAB_ + PREP_MAP_)

// scratch
__device__ __align__(128) unsigned char g_xhalf[(size_t)12544 * 16 * 128];
__device__ __align__(128) unsigned char g_whalf[(size_t)512 * 16 * 128];
__device__ int   g_vis_pos[B_ * V_];
__device__ float g_vis_base[TT_ * DEC_];   // pos_embed + view_embed + bias
__device__ float g_mask_base[TT_ * DEC_];  // pos_embed + view_embed + mask_token

// ---------------------------------------------------------------------------
// helpers
// ---------------------------------------------------------------------------
__device__ __forceinline__ uint32_t smem_u32(const void* p) {
    uint32_t a;
    asm("{ .reg .u64 t; cvta.to.shared.u64 t, %1; cvt.u32.u64 %0, t; }"
        : "=r"(a) : "l"(p));
    return a;
}
__device__ __forceinline__ void ldsm_x4(uint32_t* r, uint32_t addr) {
    asm volatile("ldmatrix.sync.aligned.m8n8.x4.shared.b16 {%0,%1,%2,%3}, [%4];"
                 : "=r"(r[0]), "=r"(r[1]), "=r"(r[2]), "=r"(r[3]) : "r"(addr));
}
__device__ __forceinline__ void mma16816(float* d, const uint32_t* a, const uint32_t* b) {
    asm volatile("mma.sync.aligned.m16n8k16.row.col.f32.f16.f16.f32 "
                 "{%0,%1,%2,%3},{%4,%5,%6,%7},{%8,%9},{%0,%1,%2,%3};"
                 : "+f"(d[0]), "+f"(d[1]), "+f"(d[2]), "+f"(d[3])
                 : "r"(a[0]), "r"(a[1]), "r"(a[2]), "r"(a[3]),
                   "r"(b[0]), "r"(b[1]));
}
__device__ __forceinline__ void cp16(uint32_t dst, const void* src) {
    asm volatile("cp.async.cg.shared.global [%0], [%1], 16;"
                 :: "r"(dst), "l"(src) : "memory");
}
#define CP_COMMIT() asm volatile("cp.async.commit_group;" ::: "memory")
#define CP_WAIT0()  asm volatile("cp.async.wait_group 0;" ::: "memory")

__device__ __forceinline__ uint32_t swz128(uint32_t off) {
    return off ^ ((off >> 3) & 0x70u);
}
__device__ __forceinline__ uint2 cvt_f4h(float4 f) {
    uint2 r;
    __half2 p0 = __floats2half2_rn(f.x, f.y);
    __half2 p1 = __floats2half2_rn(f.z, f.w);
    r.x = *(uint32_t*)&p0;
    r.y = *(uint32_t*)&p1;
    return r;
}

// ---------------------------------------------------------------------------
// Prep kernel: convert x, convert W, build epilogue tables, build vis map.
// ---------------------------------------------------------------------------
__global__ void prep_kernel(const float* __restrict__ x,
                            const float* __restrict__ Wm,
                            const float* __restrict__ bias,
                            const float* __restrict__ pos_embed,
                            const float* __restrict__ view_embed,
                            const float* __restrict__ mask_token,
                            const int* __restrict__ masked_ids) {
    const int bid = blockIdx.x;
    const int tid = threadIdx.x;   // 512

    if (bid < PREP_X_ + PREP_W_) {
        const float* src;
        unsigned char* dst;
        int row0;
        if (bid < PREP_X_) { src = x;  dst = g_xhalf; row0 = bid * 4; }
        else               { src = Wm; dst = g_whalf; row0 = (bid - PREP_X_) * 4; }
#pragma unroll
        for (int q = 0; q < 2; q++) {
            int fi  = tid + q * 512;
            int row = row0 + (fi >> 8);
            int k4  = fi & 255;
            float4 f = *(const float4*)(src + (size_t)row * ENC_ + k4 * 4);
            int ch  = k4 >> 4;
            int pos = k4 & 15;
            *(uint2*)(dst + ((size_t)row * 16 + ch) * 128 + pos * 8) = cvt_f4h(f);
        }
        return;
    }

    if (bid < PREP_X_ + PREP_W_ + PREP_TAB_) {
        // epilogue tables: 784 virtual rows = [0,392) vis_base, [392,784) mask_base
        const int v0 = (bid - PREP_X_ - PREP_W_) * 4;
        const int d  = tid;   // 512 threads = DEC
#pragma unroll
        for (int r = 0; r < 4; r++) {
            const int v = v0 + r;
            const int pos = (v < TT_) ? v : (v - TT_);
            float base = pos_embed[(size_t)pos * DEC_ + d]
                       + view_embed[(pos >= T_ ? DEC_ : 0) + d];
            if (v < TT_) g_vis_base[(size_t)pos * DEC_ + d]  = base + bias[d];
            else         g_mask_base[(size_t)pos * DEC_ + d] = base + mask_token[d];
        }
        return;
    }

    // build_map branch
    __shared__ int flags[TT_];
    __shared__ int scan[TT_];
    const int b = bid - (PREP_X_ + PREP_W_ + PREP_TAB_);
    if (tid < TT_) flags[tid] = 1;
    __syncthreads();
    if (tid < M_) flags[masked_ids[b * M_ + tid]] = 0;
    __syncthreads();
    if (tid < TT_) scan[tid] = flags[tid];
    __syncthreads();
    for (int off = 1; off < TT_; off <<= 1) {
        int v = 0;
        if (tid < TT_ && tid >= off) v = scan[tid - off];
        __syncthreads();
        if (tid < TT_) scan[tid] += v;
        __syncthreads();
    }
    if (tid < TT_ && flags[tid]) g_vis_pos[b * V_ + scan[tid] - 1] = tid;
}

// ---------------------------------------------------------------------------
// Fused kernel: bids [0,784) GEMM 128x64 tiles (cp.async 2-stage, fp16 mma,
// table-based scatter epilogue), bids [784,880) masked fill (row copy).
// ---------------------------------------------------------------------------
__global__ __launch_bounds__(256, 4)
void gemm_fused_kernel(const int* __restrict__ masked_ids,
                       float* __restrict__ out) {
    const int bid = blockIdx.x;
    const int tid = threadIdx.x;

    // ======================= FILL branch (pure row copy) ==================
    if (bid >= NGEMM_) {
        const int f = bid - NGEMM_;
        const int d0 = (tid & 127) * 4;
        const int half = tid >> 7;
        for (int w = f * 2 + half; w < NWORK_; w += NFILL_ * 2) {
            const int b = w / M_;
            const int m = w - b * M_;
            const int pos = masked_ids[b * M_ + m];
            float4 v = *(const float4*)(g_mask_base + (size_t)pos * DEC_ + d0);
            *(float4*)(out + ((size_t)b * TT_ + pos) * DEC_ + d0) = v;
        }
        return;
    }

    // ======================= GEMM branch =======================
    extern __shared__ char smem[];
    const uint32_t sb = smem_u32(smem);
    const int lid = tid & 31;
    const int wid = tid >> 5;
    const int wm  = wid & 3;          // 4 m-warps x 32 rows
    const int wn  = wid >> 2;         // 2 n-warps x 32 cols
    const int m0  = (bid % 98) * 128;
    const int n0  = (bid / 98) * 64;

    const unsigned char* asrc = g_xhalf + (size_t)m0 * 2048;   // 16*128 B/row
    const unsigned char* bsrc = g_whalf + (size_t)n0 * 2048;

    // cp.async per-thread mapping: u = tid + j*256, row = u>>3, seg = u&7
    const int curow = tid >> 3;
    const int cuseg = tid & 7;

    // ldmatrix lane constants (SW128: phys = row*128 + (c ^ ((row&7)<<4)))
    const int ar   = lid & 15;
    const int akh  = lid >> 4;
    const uint32_t xrA   = (uint32_t)((ar & 7) << 4);
    const uint32_t aoff0 = (uint32_t)((wm * 32 + ar) * 128);
    const int brow = ((lid >> 4) << 3) + (lid & 7);
    const int bkh  = (lid >> 3) & 1;
    const uint32_t xrB   = (uint32_t)((brow & 7) << 4);
    const uint32_t boff0 = B_OFF + (uint32_t)((wn * 32 + brow) * 128);

    float acc[2][4][4];
#pragma unroll
    for (int i = 0; i < 2; i++)
#pragma unroll
        for (int j = 0; j < 4; j++)
#pragma unroll
            for (int c = 0; c < 4; c++) acc[i][j][c] = 0.0f;

    auto issue = [&](int s, int ch) {
        const uint32_t sa = sb + (uint32_t)s * STG_BYTES;
#pragma unroll
        for (int j = 0; j < 4; j++) {
            int u = tid + j * 256;
            uint32_t d = sa + swz128((uint32_t)u * 16);
            cp16(d, asrc + (size_t)(curow + j * 32) * 2048 + ch * 128 + cuseg * 16);
        }
#pragma unroll
        for (int j = 0; j < 2; j++) {
            int u = tid + j * 256;
            uint32_t d = sa + B_OFF + swz128((uint32_t)u * 16);
            cp16(d, bsrc + (size_t)(curow + j * 32) * 2048 + ch * 128 + cuseg * 16);
        }
    };

    // ---- prologue: stage 0 <- chunk 0 ----
    issue(0, 0); CP_COMMIT();

    for (int ch = 0; ch < NCH_; ch++) {
        CP_WAIT0();
        __syncthreads();
        if (ch + 1 < NCH_) issue((ch + 1) & 1, ch + 1);
        CP_COMMIT();

        const uint32_t stg = sb + (uint32_t)(ch & 1) * STG_BYTES;
#pragma unroll
        for (int ks = 0; ks < 4; ks++) {
            const uint32_t cA = (uint32_t)(ks * 32 + akh * 16);
            const uint32_t cB = (uint32_t)(ks * 32 + bkh * 16);
            uint32_t aH[2][4];
#pragma unroll
            for (int i = 0; i < 2; i++) {
                uint32_t ad = stg + aoff0 + (uint32_t)(i * 2048) + (cA ^ xrA);
                ldsm_x4(aH[i], ad);
            }
#pragma unroll
            for (int jj = 0; jj < 2; jj++) {
                uint32_t bd = stg + boff0 + (uint32_t)(jj * 2048) + (cB ^ xrB);
                uint32_t bh[4];
                ldsm_x4(bh, bd);
#pragma unroll
                for (int i = 0; i < 2; i++) {
                    mma16816(acc[i][2 * jj],     aH[i], bh);
                    mma16816(acc[i][2 * jj + 1], aH[i], bh + 2);
                }
            }
        }
    }

    // ---- epilogue: scatter, single table read ----
    const int qrow = lid >> 2;
    const int qcol = (lid & 3) * 2;
#pragma unroll
    for (int i = 0; i < 2; i++) {
#pragma unroll
        for (int half = 0; half < 2; half++) {
            const int m   = wm * 32 + i * 16 + qrow + half * 8;
            const int r   = m0 + m;
            const int bb  = r / V_;
            const int pos = g_vis_pos[r];
            const float* base = g_vis_base + (size_t)pos * DEC_;
            float* op = out + ((size_t)bb * TT_ + pos) * DEC_;
#pragma unroll
            for (int j = 0; j < 4; j++) {
                const int n = n0 + wn * 32 + j * 8 + qcol;
                float2 bv = *(const float2*)(base + n);
                float2 o;
                o.x = acc[i][j][half * 2 + 0] + bv.x;
                o.y = acc[i][j][half * 2 + 1] + bv.y;
                *(float2*)(op + n) = o;
            }
        }
    }
}

// ---------------------------------------------------------------------------
extern "C" void kernel_launch(void* const* d_in, const int* in_sizes, int n_in,
                              void* d_out, int out_size) {
    const float* x          = (const float*)d_in[0];
    const int*   masked_ids = (const int*)d_in[1];
    const float* Wm         = (const float*)d_in[2];
    const float* bias       = (const float*)d_in[3];
    const float* mask_token = (const float*)d_in[4];
    const float* pos_embed  = (const float*)d_in[5];
    const float* view_embed = (const float*)d_in[6];
    float*       out        = (float*)d_out;

    cudaFuncSetAttribute(gemm_fused_kernel,
                         cudaFuncAttributeMaxDynamicSharedMemorySize, SMEM_TOTAL);

    prep_kernel<<<PREP_GRID_, 512>>>(x, Wm, bias, pos_embed, view_embed,
                                     mask_token, masked_ids);
    gemm_fused_kernel<<<NGEMM_ + NFILL_, 256, SMEM_TOTAL>>>(masked_ids, out);
}